// round 13
// baseline (speedup 1.0000x reference)
#include <cuda_runtime.h>

#define N_CELLS 50000
#define HID 64
#define DEG 16
#define KND 4

// ---- scratch (device globals; no allocations allowed) ----
__device__ float g_cent[N_CELLS * 3];        // cell centroids
__device__ float g_P[(size_t)N_CELLS * 128]; // [A = F@W1a + b1 | G = F@W1b]
__device__ float g_hsum[(size_t)N_CELLS * HID]; // sum_j silu(pre_j)
__device__ float g_sS[(size_t)N_CELLS * HID];   // silu(S_pre)
__device__ float g_W2u[HID * HID];           // (W2/16) @ Wu1[64:128]
__device__ float g_bc[HID];                  // bu1 + b2 @ Wu1[64:128]

static __device__ __forceinline__ float silu_f(float x) {
    // silu(x) = x*sigmoid(x) = xh + xh*tanh(xh), xh = x/2   (1 MUFU)
    float t, xh = 0.5f * x;
    asm("tanh.approx.f32 %0, %1;" : "=f"(t) : "f"(xh));
    return fmaf(xh, t, xh);
}
static __device__ __forceinline__ float sqrt_approx(float x) {
    float r;
    asm("sqrt.approx.f32 %0, %1;" : "=f"(r) : "f"(x));
    return r;
}

// ---- combine weights: W2u = (W2 @ Wu1b)/16 ; bc = bu1 + b2 @ Wu1b ----
__global__ void k_combine(const float* __restrict__ W2, const float* __restrict__ b2,
                          const float* __restrict__ Wu1, const float* __restrict__ bu1) {
    int k = threadIdx.x;  // 0..63
    int r = blockIdx.x;   // 0..63 weight rows, 64 => bias
    if (r < HID) {
        float acc = 0.f;
        #pragma unroll 8
        for (int m = 0; m < HID; m++)
            acc = fmaf(W2[r * HID + m], Wu1[(HID + m) * HID + k], acc);
        g_W2u[r * HID + k] = acc * (1.0f / 16.0f);
    } else {
        float acc = bu1[k];
        for (int m = 0; m < HID; m++)
            acc = fmaf(b2[m], Wu1[(HID + m) * HID + k], acc);
        g_bc[k] = acc;
    }
}

// ---- centroids: cent[i] = mean of positions[4i..4i+4) ----
__global__ void k_cent(const float* __restrict__ pos) {
    int i = blockIdx.x * blockDim.x + threadIdx.x;
    if (i >= N_CELLS) return;
    const float4* p = (const float4*)(pos + (size_t)i * 12);
    float4 v0 = p[0], v1 = p[1], v2 = p[2];
    g_cent[3 * i + 0] = 0.25f * (v0.x + v0.w + v1.z + v2.y);
    g_cent[3 * i + 1] = 0.25f * (v0.y + v1.x + v1.w + v2.z);
    g_cent[3 * i + 2] = 0.25f * (v0.z + v1.y + v2.x + v2.w);
}

// ---- P[N,128] = F @ [W1a | W1b] (+ b1 on first 64 cols) ----
// column-owner: thread k holds its 64-entry weight column in registers,
// features broadcast from smem.
__global__ __launch_bounds__(128) void k_pre(const float* __restrict__ F,
                                             const float* __restrict__ W1,
                                             const float* __restrict__ b1) {
    __shared__ float fs[32 * 64];
    int k = threadIdx.x;
    float w[64];
    float bias;
    if (k < 64) {
        #pragma unroll
        for (int r = 0; r < 64; r++) w[r] = W1[r * 64 + k];
        bias = b1[k];
    } else {
        #pragma unroll
        for (int r = 0; r < 64; r++) w[r] = W1[(64 + r) * 64 + (k - 64)];
        bias = 0.f;
    }
    int c0 = blockIdx.x * 32;
    int nc = min(32, N_CELLS - c0);
    const float4* src = (const float4*)(F + (size_t)c0 * 64);
    float4* dst = (float4*)fs;
    for (int t = threadIdx.x; t < nc * 16; t += 128) dst[t] = src[t];
    __syncthreads();
    for (int c = 0; c < nc; c++) {
        float a0 = bias, a1 = 0.f;
        #pragma unroll
        for (int r = 0; r < 64; r += 2) {
            a0 = fmaf(fs[c * 64 + r],     w[r],     a0);
            a1 = fmaf(fs[c * 64 + r + 1], w[r + 1], a1);
        }
        g_P[(size_t)(c0 + c) * 128 + k] = a0 + a1;
    }
}

// ---- pair phase: hsum[i] = sum_d silu(A_i + G_j + geom_ij * W1[128]) ----
// one warp per cell, each lane owns 2 hidden dims (float2)
__global__ __launch_bounds__(256) void k_pair(const int* __restrict__ nbr,
                                              const float* __restrict__ W1) {
    int gw = (blockIdx.x * 256 + threadIdx.x) >> 5;
    int lane = threadIdx.x & 31;
    if (gw >= N_CELLS) return;
    int i = gw;
    float2 a = *(const float2*)&g_P[(size_t)i * 128 + 2 * lane];
    float2 w = *(const float2*)&W1[128 * 64 + 2 * lane];
    float cix = g_cent[3 * i], ciy = g_cent[3 * i + 1], ciz = g_cent[3 * i + 2];
    const int4* nb = (const int4*)(nbr + (size_t)i * 16);
    int4 n0 = nb[0], n1 = nb[1], n2 = nb[2], n3 = nb[3];
    int js[16] = {n0.x, n0.y, n0.z, n0.w, n1.x, n1.y, n1.z, n1.w,
                  n2.x, n2.y, n2.z, n2.w, n3.x, n3.y, n3.z, n3.w};
    float hx = 0.f, hy = 0.f;
    #pragma unroll
    for (int d = 0; d < 16; d++) {
        int j = js[d];
        float dx = cix - g_cent[3 * j];
        float dy = ciy - g_cent[3 * j + 1];
        float dz = ciz - g_cent[3 * j + 2];
        float geom = sqrt_approx(fmaf(dx, dx, fmaf(dy, dy, dz * dz)));
        float2 g = *(const float2*)&g_P[(size_t)j * 128 + 64 + 2 * lane];
        float p0 = fmaf(geom, w.x, a.x + g.x);
        float p1 = fmaf(geom, w.y, a.y + g.y);
        hx += silu_f(p0);
        hy += silu_f(p1);
    }
    *(float2*)&g_hsum[(size_t)i * 64 + 2 * lane] = make_float2(hx, hy);
}

// ---- update stage 1: sS = silu(F@Wu1a + hsum@W2u + bc) ----
__global__ __launch_bounds__(64) void k_upd1(const float* __restrict__ F,
                                             const float* __restrict__ Wu1) {
    __shared__ float fs[32 * 64];
    __shared__ float hs[32 * 64];
    int k = threadIdx.x;
    float wa[64], wb[64];
    #pragma unroll
    for (int r = 0; r < 64; r++) {
        wa[r] = Wu1[r * 64 + k];
        wb[r] = g_W2u[r * 64 + k];
    }
    float bias = g_bc[k];
    int c0 = blockIdx.x * 32;
    int nc = min(32, N_CELLS - c0);
    {
        const float4* s1 = (const float4*)(F + (size_t)c0 * 64);
        const float4* s2 = (const float4*)(g_hsum + (size_t)c0 * 64);
        float4* d1 = (float4*)fs;
        float4* d2 = (float4*)hs;
        for (int t = threadIdx.x; t < nc * 16; t += 64) {
            d1[t] = s1[t];
            d2[t] = s2[t];
        }
    }
    __syncthreads();
    for (int c = 0; c < nc; c++) {
        float a0 = bias, a1 = 0.f;
        #pragma unroll
        for (int r = 0; r < 64; r += 2) {
            a0 = fmaf(fs[c * 64 + r],     wa[r],     a0);
            a1 = fmaf(fs[c * 64 + r + 1], wa[r + 1], a1);
            a0 = fmaf(hs[c * 64 + r],     wb[r],     a0);
            a1 = fmaf(hs[c * 64 + r + 1], wb[r + 1], a1);
        }
        g_sS[(size_t)(c0 + c) * 64 + k] = silu_f(a0 + a1);
    }
}

// ---- update stage 2: out = F + sS@Wu2 + bu2 ----
__global__ __launch_bounds__(64) void k_upd2(const float* __restrict__ F,
                                             const float* __restrict__ Wu2,
                                             const float* __restrict__ bu2,
                                             float* __restrict__ out) {
    __shared__ float ss[32 * 64];
    int k = threadIdx.x;
    float w[64];
    #pragma unroll
    for (int r = 0; r < 64; r++) w[r] = Wu2[r * 64 + k];
    float bias = bu2[k];
    int c0 = blockIdx.x * 32;
    int nc = min(32, N_CELLS - c0);
    const float4* s1 = (const float4*)(g_sS + (size_t)c0 * 64);
    float4* d1 = (float4*)ss;
    for (int t = threadIdx.x; t < nc * 16; t += 64) d1[t] = s1[t];
    __syncthreads();
    for (int c = 0; c < nc; c++) {
        float a0 = bias, a1 = 0.f;
        #pragma unroll
        for (int r = 0; r < 64; r += 2) {
            a0 = fmaf(ss[c * 64 + r],     w[r],     a0);
            a1 = fmaf(ss[c * 64 + r + 1], w[r + 1], a1);
        }
        size_t idx = (size_t)(c0 + c) * 64 + k;
        out[idx] = F[idx] + a0 + a1;
    }
}

extern "C" void kernel_launch(void* const* d_in, const int* in_sizes, int n_in,
                              void* d_out, int out_size) {
    const float* F   = (const float*)d_in[0];
    const float* pos = (const float*)d_in[1];
    const int*   nbr = (const int*)d_in[2];
    const float* W1  = (const float*)d_in[3];
    const float* b1  = (const float*)d_in[4];
    const float* W2  = (const float*)d_in[5];
    const float* b2  = (const float*)d_in[6];
    const float* Wu1 = (const float*)d_in[7];
    const float* bu1 = (const float*)d_in[8];
    const float* Wu2 = (const float*)d_in[9];
    const float* bu2 = (const float*)d_in[10];
    float* out = (float*)d_out;

    k_combine<<<65, 64>>>(W2, b2, Wu1, bu1);
    k_cent<<<(N_CELLS + 255) / 256, 256>>>(pos);
    k_pre<<<(N_CELLS + 31) / 32, 128>>>(F, W1, b1);
    k_pair<<<(N_CELLS * 32 + 255) / 256, 256>>>(nbr, W1);
    k_upd1<<<(N_CELLS + 31) / 32, 64>>>(F, Wu1);
    k_upd2<<<(N_CELLS + 31) / 32, 64>>>(F, Wu2, bu2, out);

    // second output: positions passthrough
    long long nh = (long long)N_CELLS * HID;
    long long np = (long long)N_CELLS * KND * 3;
    if ((long long)out_size >= nh + np) {
        cudaMemcpyAsync(out + nh, pos, (size_t)np * sizeof(float),
                        cudaMemcpyDeviceToDevice, 0);
    }
}